// round 16
// baseline (speedup 1.0000x reference)
#include <cuda_runtime.h>
#include <cstdint>

#define TT 256
#define CC 195
#define HH 8
#define JJ 24            // qkv cols: q(0-7) k(8-15) v(16-23)
#define NT 128
#define KPAD 200
#define NCH 25
#define QKVSTR 28        // qkv row stride (112B, 16B-aligned, LDSM-safe)
#define PSTR 20          // P row stride (80B: 16B-aligned rows, LDSM banks 20r%32 distinct)
#define PBUF (64 * PSTR) // 1280 floats per warp
#define SMEM_BYTES ((TT * QKVSTR + 4 * PBUF) * 4)   // 49152

typedef unsigned long long u64;

__device__ __forceinline__ uint32_t f2tf32(float f) {
    uint32_t r; asm("cvt.rna.tf32.f32 %0, %1;" : "=r"(r) : "f"(f)); return r;
}
__device__ __forceinline__ void ldsm4(uint32_t* d, unsigned addr) {
    asm volatile("ldmatrix.sync.aligned.m8n8.x4.shared.b16 {%0,%1,%2,%3}, [%4];"
                 : "=r"(d[0]), "=r"(d[1]), "=r"(d[2]), "=r"(d[3]) : "r"(addr));
}
__device__ __forceinline__ void mma_tf32(float* c, const uint32_t* a, const uint32_t* b) {
    asm volatile("mma.sync.aligned.m16n8k8.row.col.f32.tf32.tf32.f32 "
                 "{%0,%1,%2,%3}, {%4,%5,%6,%7}, {%8,%9}, {%0,%1,%2,%3};"
                 : "+f"(c[0]), "+f"(c[1]), "+f"(c[2]), "+f"(c[3])
                 : "r"(a[0]), "r"(a[1]), "r"(a[2]), "r"(a[3]), "r"(b[0]), "r"(b[1]));
}

// validated A-fragment gmem mapping (R14/R15)
__device__ __forceinline__ void load_a_chunk(const float* __restrict__ xg,
                                             int c0, int ar, int ac,
                                             float* ra, bool tail) {
    #pragma unroll
    for (int mt = 0; mt < 4; mt++) {
        const float* p0 = xg + (long)(16 * mt + ar) * CC;
        const float* p1 = p0 + 8 * CC;
        if (!tail) {
            ra[4 * mt + 0] = __ldg(p0 + c0 + ac);
            ra[4 * mt + 1] = __ldg(p1 + c0 + ac);
            ra[4 * mt + 2] = __ldg(p0 + c0 + ac + 4);
            ra[4 * mt + 3] = __ldg(p1 + c0 + ac + 4);
        } else {
            const bool v0 = (c0 + ac) < CC;
            ra[4 * mt + 0] = v0 ? __ldg(p0 + c0 + ac) : 0.f;
            ra[4 * mt + 1] = v0 ? __ldg(p1 + c0 + ac) : 0.f;
            ra[4 * mt + 2] = 0.f;
            ra[4 * mt + 3] = 0.f;
        }
    }
}

extern __shared__ __align__(16) float smem[];

__global__ __launch_bounds__(NT, 4)
void head_attn_kernel(const float* __restrict__ x,
                      const float* __restrict__ Wq,
                      const float* __restrict__ Wk,
                      const float* __restrict__ Wv,
                      float* __restrict__ out)
{
    float* w_s = smem;

    const int tid = threadIdx.x;
    const int b   = blockIdx.x;
    const int w   = tid >> 5;
    const int l   = tid & 31;

    const float kScale = 1.4426950408889634f * rsqrtf((float)CC);  // 1/sqrt(C)*log2(e)

    // ---- stage W as [c][24], tf32 bits, K rows >= CC zeroed ----
    for (int i = tid; i < KPAD * HH; i += NT) {
        int c = i >> 3, h = i & 7;
        float vq = 0.f, vk = 0.f, vv = 0.f;
        if (c < CC) {
            vq = Wq[c * HH + h] * kScale;
            vk = Wk[c * HH + h];
            vv = Wv[c * HH + h];
        }
        w_s[c * JJ +      h] = __uint_as_float(f2tf32(vq));
        w_s[c * JJ +  8 + h] = __uint_as_float(f2tf32(vk));
        w_s[c * JJ + 16 + h] = __uint_as_float(f2tf32(vv));
    }
    __syncthreads();

    // ---- phase 1: tf32 MMA projection, direct-LDG A fragments (R14) ----
    const float* xg = x + ((long)b * TT + 64 * w) * CC;
    const int ar = l >> 2;
    const int ac = l & 3;
    const int bn = l >> 2;
    const int bk = l & 3;

    float cacc[48];
    #pragma unroll
    for (int i = 0; i < 48; i++) cacc[i] = 0.f;

    float ra[16], rb[16];
    load_a_chunk(xg, 0, ar, ac, ra, false);

    #pragma unroll 1
    for (int ch = 0; ch < NCH; ch++) {
        if (ch + 1 < NCH)
            load_a_chunk(xg, (ch + 1) * 8, ar, ac, rb, (ch + 1) == NCH - 1);

        const int kr = ch * 8 + bk;
        uint32_t bh[6];
        #pragma unroll
        for (int nt = 0; nt < 3; nt++) {
            bh[2 * nt]     = __float_as_uint(w_s[kr * JJ       + nt * 8 + bn]);
            bh[2 * nt + 1] = __float_as_uint(w_s[(kr + 4) * JJ + nt * 8 + bn]);
        }
        #pragma unroll
        for (int mt = 0; mt < 4; mt++) {
            uint32_t ah[4];
            #pragma unroll
            for (int i = 0; i < 4; i++) ah[i] = f2tf32(ra[4 * mt + i]);
            #pragma unroll
            for (int nt = 0; nt < 3; nt++)
                mma_tf32(&cacc[(mt * 3 + nt) * 4], ah, &bh[2 * nt]);
        }
        #pragma unroll
        for (int i = 0; i < 16; i++) ra[i] = rb[i];
    }

    __syncthreads();   // w_s reads done before qkv overlay

    // ---- epilogue: C fragments -> qkv [256][28] (validated) ----
    float* qkv = smem;
    {
        const int erow = 64 * w + (l >> 2);
        const int ecol = 2 * (l & 3);
        #pragma unroll
        for (int mt = 0; mt < 4; mt++) {
            #pragma unroll
            for (int nt = 0; nt < 3; nt++) {
                const float* cf = &cacc[(mt * 3 + nt) * 4];
                float* p = &qkv[(erow + 16 * mt) * QKVSTR + nt * 8 + ecol];
                *reinterpret_cast<float2*>(p)              = make_float2(cf[0], cf[1]);
                *reinterpret_cast<float2*>(p + 8 * QKVSTR) = make_float2(cf[2], cf[3]);
            }
        }
    }
    __syncthreads();

    // ---- phase 2: tensor-core causal attention, 16-key tiles ----
    const int wblk = (w + b) & 3;                    // SMSP balance rotation
    float* pbuf = smem + TT * QKVSTR + w * PBUF;     // warp-private P tile [64][20]

    const unsigned lrow  = (l & 7) + 8 * ((l >> 3) & 1);
    const unsigned lcolo = (l >> 4) * 16;
    const unsigned qbase = (unsigned)__cvta_generic_to_shared(qkv)
                         + (64 * wblk + lrow) * (QKVSTR * 4) + lcolo;
    const unsigned pbase = (unsigned)__cvta_generic_to_shared(pbuf)
                         + lrow * (PSTR * 4) + lcolo;

    // Q A-fragments: loaded once
    uint32_t qa[16];
    #pragma unroll
    for (int mt = 0; mt < 4; mt++) {
        uint32_t u[4];
        ldsm4(u, qbase + mt * 16 * QKVSTR * 4);
        #pragma unroll
        for (int i = 0; i < 4; i++) qa[4 * mt + i] = f2tf32(__uint_as_float(u[i]));
    }

    float oacc[16];
    float ssum[8];
    #pragma unroll
    for (int i = 0; i < 16; i++) oacc[i] = 0.f;
    #pragma unroll
    for (int i = 0; i < 8; i++) ssum[i] = 0.f;

    const int niter = 4 * (wblk + 1);      // 16-key tiles
    const int diter = 4 * wblk;            // first tile needing causal mask
    const int r1b   = 64 * wblk + (l >> 2);
    const int keyc  = 2 * (l & 3);

    #pragma unroll 1
    for (int it = 0; it < niter; it++) {
        const int kb = 16 * it;

        // K B-fragments for 2 n8 tiles (banks all-distinct)
        uint32_t kB[4];
        #pragma unroll
        for (int nt2 = 0; nt2 < 2; nt2++) {
            const int krow = kb + 8 * nt2 + (l >> 2);
            kB[2 * nt2]     = f2tf32(qkv[krow * QKVSTR + 8 + (l & 3)]);
            kB[2 * nt2 + 1] = f2tf32(qkv[krow * QKVSTR + 8 + (l & 3) + 4]);
        }

        // S = Q*K^T: 8 MMAs
        float sfr[32];
        #pragma unroll
        for (int i = 0; i < 32; i++) sfr[i] = 0.f;
        #pragma unroll
        for (int mt = 0; mt < 4; mt++) {
            mma_tf32(&sfr[(mt * 2 + 0) * 4], &qa[4 * mt], &kB[0]);
            mma_tf32(&sfr[(mt * 2 + 1) * 4], &qa[4 * mt], &kB[2]);
        }

        // V B-fragments (issued early: LDS latency hides under exp2/STS)
        uint32_t vB[4];
        #pragma unroll
        for (int c8 = 0; c8 < 2; c8++) {
            const int vrow = kb + 8 * c8 + (l & 3);
            vB[2 * c8]     = f2tf32(qkv[vrow * QKVSTR + 16 + (l >> 2)]);
            vB[2 * c8 + 1] = f2tf32(qkv[(vrow + 4) * QKVSTR + 16 + (l >> 2)]);
        }

        // exp2 (+ causal mask), row sums, P -> warp buffer
        const bool diag = (it >= diter);
        #pragma unroll
        for (int mt = 0; mt < 4; mt++) {
            const int rr1 = r1b + 16 * mt, rr2 = rr1 + 8;
            #pragma unroll
            for (int nt2 = 0; nt2 < 2; nt2++) {
                const float* sf = &sfr[(mt * 2 + nt2) * 4];
                const int key0 = kb + 8 * nt2 + keyc;
                float p0 = exp2f(sf[0]);
                float p1 = exp2f(sf[1]);
                float p2 = exp2f(sf[2]);
                float p3 = exp2f(sf[3]);
                if (diag) {
                    p0 = (key0     <= rr1) ? p0 : 0.f;
                    p1 = (key0 + 1 <= rr1) ? p1 : 0.f;
                    p2 = (key0     <= rr2) ? p2 : 0.f;
                    p3 = (key0 + 1 <= rr2) ? p3 : 0.f;
                }
                ssum[2 * mt]     += p0 + p1;
                ssum[2 * mt + 1] += p2 + p3;
                float* pp = &pbuf[(16 * mt + (l >> 2)) * PSTR + 8 * nt2 + keyc];
                *reinterpret_cast<float2*>(pp)            = make_float2(p0, p1);
                *reinterpret_cast<float2*>(pp + 8 * PSTR) = make_float2(p2, p3);
            }
        }
        __syncwarp();   // P visible to all lanes

        // AV: A = P tile (k=16 -> 2 k8 chunks via LDSM), B = V
        #pragma unroll
        for (int mt = 0; mt < 4; mt++) {
            #pragma unroll
            for (int c8 = 0; c8 < 2; c8++) {
                uint32_t u[4], pa[4];
                ldsm4(u, pbase + mt * 16 * PSTR * 4 + c8 * 32);
                #pragma unroll
                for (int i = 0; i < 4; i++) pa[i] = f2tf32(__uint_as_float(u[i]));
                mma_tf32(&oacc[4 * mt], pa, &vB[2 * c8]);
            }
        }
        __syncwarp();   // WAR before next tile overwrites pbuf
    }

    // reduce row sums across the quad
    #pragma unroll
    for (int i = 0; i < 8; i++) {
        ssum[i] += __shfl_xor_sync(0xFFFFFFFF, ssum[i], 1);
        ssum[i] += __shfl_xor_sync(0xFFFFFFFF, ssum[i], 2);
    }

    // normalize + write O directly from C fragments
    float* ob = out + (long)b * TT * HH;
    #pragma unroll
    for (int mt = 0; mt < 4; mt++) {
        const int rr1 = r1b + 16 * mt;
        const float i1 = __fdividef(1.f, ssum[2 * mt]);
        const float i2 = __fdividef(1.f, ssum[2 * mt + 1]);
        *reinterpret_cast<float2*>(&ob[rr1 * HH + keyc]) =
            make_float2(oacc[4 * mt + 0] * i1, oacc[4 * mt + 1] * i1);
        *reinterpret_cast<float2*>(&ob[(rr1 + 8) * HH + keyc]) =
            make_float2(oacc[4 * mt + 2] * i2, oacc[4 * mt + 3] * i2);
    }
}

extern "C" void kernel_launch(void* const* d_in, const int* in_sizes, int n_in,
                              void* d_out, int out_size)
{
    const float* x  = (const float*)d_in[0];
    const float* Wq = (const float*)d_in[1];
    const float* Wk = (const float*)d_in[2];
    const float* Wv = (const float*)d_in[3];
    float* out = (float*)d_out;

    (void)cudaFuncSetAttribute(head_attn_kernel,
                               cudaFuncAttributeMaxDynamicSharedMemorySize,
                               SMEM_BYTES);
    head_attn_kernel<<<1024, NT, SMEM_BYTES>>>(x, Wq, Wk, Wv, out);
}

// round 17
// speedup vs baseline: 1.1252x; 1.1252x over previous
#include <cuda_runtime.h>
#include <cstdint>

#define TT 256
#define CC 195
#define HH 8
#define JJ 24            // qkv cols: q(0-7) k(8-15) v(16-23)
#define NT 128
#define KPAD 200
#define NCH 25
#define QKVSTR 28        // qkv row stride (112B, 16B-aligned, LDSM-safe)
#define PSTR 12          // P row stride (48B, LDSM banks 12r%32 distinct)
#define PBUF (64 * PSTR) // 768 floats per warp

typedef unsigned long long u64;

__device__ __forceinline__ uint32_t f2tf32(float f) {
    uint32_t r; asm("cvt.rna.tf32.f32 %0, %1;" : "=r"(r) : "f"(f)); return r;
}
__device__ __forceinline__ void ldsm4(uint32_t* d, unsigned addr) {
    asm volatile("ldmatrix.sync.aligned.m8n8.x4.shared.b16 {%0,%1,%2,%3}, [%4];"
                 : "=r"(d[0]), "=r"(d[1]), "=r"(d[2]), "=r"(d[3]) : "r"(addr));
}
__device__ __forceinline__ void mma_tf32(float* c, const uint32_t* a, const uint32_t* b) {
    asm volatile("mma.sync.aligned.m16n8k8.row.col.f32.tf32.tf32.f32 "
                 "{%0,%1,%2,%3}, {%4,%5,%6,%7}, {%8,%9}, {%0,%1,%2,%3};"
                 : "+f"(c[0]), "+f"(c[1]), "+f"(c[2]), "+f"(c[3])
                 : "r"(a[0]), "r"(a[1]), "r"(a[2]), "r"(a[3]), "r"(b[0]), "r"(b[1]));
}

// validated A-fragment gmem mapping (R14/R15)
__device__ __forceinline__ void load_a_chunk(const float* __restrict__ xg,
                                             int c0, int ar, int ac,
                                             float* ra, bool tail) {
    #pragma unroll
    for (int mt = 0; mt < 4; mt++) {
        const float* p0 = xg + (long)(16 * mt + ar) * CC;
        const float* p1 = p0 + 8 * CC;
        if (!tail) {
            ra[4 * mt + 0] = __ldg(p0 + c0 + ac);
            ra[4 * mt + 1] = __ldg(p1 + c0 + ac);
            ra[4 * mt + 2] = __ldg(p0 + c0 + ac + 4);
            ra[4 * mt + 3] = __ldg(p1 + c0 + ac + 4);
        } else {
            const bool v0 = (c0 + ac) < CC;
            ra[4 * mt + 0] = v0 ? __ldg(p0 + c0 + ac) : 0.f;
            ra[4 * mt + 1] = v0 ? __ldg(p1 + c0 + ac) : 0.f;
            ra[4 * mt + 2] = 0.f;
            ra[4 * mt + 3] = 0.f;
        }
    }
}

__global__ __launch_bounds__(NT, 4)
void head_attn_kernel(const float* __restrict__ x,
                      const float* __restrict__ Wq,
                      const float* __restrict__ Wk,
                      const float* __restrict__ Wv,
                      float* __restrict__ out)
{
    // [ qkv/w_s region: 7168 floats | 4 x warp P buffer: 768 floats ] = 40960B
    __shared__ __align__(16) float smem[TT * QKVSTR + 4 * PBUF];
    float* w_s = smem;

    const int tid = threadIdx.x;
    const int b   = blockIdx.x;
    const int w   = tid >> 5;
    const int l   = tid & 31;

    const float kScale = 1.4426950408889634f * rsqrtf((float)CC);  // 1/sqrt(C)*log2(e)

    // ---- stage W as [c][24], tf32 bits, K rows >= CC zeroed ----
    for (int i = tid; i < KPAD * HH; i += NT) {
        int c = i >> 3, h = i & 7;
        float vq = 0.f, vk = 0.f, vv = 0.f;
        if (c < CC) {
            vq = Wq[c * HH + h] * kScale;
            vk = Wk[c * HH + h];
            vv = Wv[c * HH + h];
        }
        w_s[c * JJ +      h] = __uint_as_float(f2tf32(vq));
        w_s[c * JJ +  8 + h] = __uint_as_float(f2tf32(vk));
        w_s[c * JJ + 16 + h] = __uint_as_float(f2tf32(vv));
    }
    __syncthreads();

    // ---- phase 1: tf32 MMA projection, direct-LDG A fragments (R14) ----
    const float* xg = x + ((long)b * TT + 64 * w) * CC;
    const int ar = l >> 2;
    const int ac = l & 3;
    const int bn = l >> 2;
    const int bk = l & 3;

    float cacc[48];
    #pragma unroll
    for (int i = 0; i < 48; i++) cacc[i] = 0.f;

    float ra[16], rb[16];
    load_a_chunk(xg, 0, ar, ac, ra, false);

    #pragma unroll 1
    for (int ch = 0; ch < NCH; ch++) {
        if (ch + 1 < NCH)
            load_a_chunk(xg, (ch + 1) * 8, ar, ac, rb, (ch + 1) == NCH - 1);

        const int kr = ch * 8 + bk;
        uint32_t bh[6];
        #pragma unroll
        for (int nt = 0; nt < 3; nt++) {
            bh[2 * nt]     = __float_as_uint(w_s[kr * JJ       + nt * 8 + bn]);
            bh[2 * nt + 1] = __float_as_uint(w_s[(kr + 4) * JJ + nt * 8 + bn]);
        }
        #pragma unroll
        for (int mt = 0; mt < 4; mt++) {
            uint32_t ah[4];
            #pragma unroll
            for (int i = 0; i < 4; i++) ah[i] = f2tf32(ra[4 * mt + i]);
            #pragma unroll
            for (int nt = 0; nt < 3; nt++)
                mma_tf32(&cacc[(mt * 3 + nt) * 4], ah, &bh[2 * nt]);
        }
        #pragma unroll
        for (int i = 0; i < 16; i++) ra[i] = rb[i];
    }

    __syncthreads();   // w_s reads done before qkv overlay

    // ---- epilogue: C fragments -> qkv [256][28] (validated) ----
    float* qkv = smem;
    {
        const int erow = 64 * w + (l >> 2);
        const int ecol = 2 * (l & 3);
        #pragma unroll
        for (int mt = 0; mt < 4; mt++) {
            #pragma unroll
            for (int nt = 0; nt < 3; nt++) {
                const float* cf = &cacc[(mt * 3 + nt) * 4];
                float* p = &qkv[(erow + 16 * mt) * QKVSTR + nt * 8 + ecol];
                *reinterpret_cast<float2*>(p)              = make_float2(cf[0], cf[1]);
                *reinterpret_cast<float2*>(p + 8 * QKVSTR) = make_float2(cf[2], cf[3]);
            }
        }
    }
    __syncthreads();

    // ---- phase 2: tensor-core causal attention, chunk-pipelined (R15 tile) ----
    const int wblk = (w + b) & 3;                  // SMSP balance rotation
    float* pbuf = smem + TT * QKVSTR + w * PBUF;   // warp-private P tile [64][12]

    const unsigned lrow  = (l & 7) + 8 * ((l >> 3) & 1);
    const unsigned lcolo = (l >> 4) * 16;
    const unsigned qbase = (unsigned)__cvta_generic_to_shared(qkv)
                         + (64 * wblk + lrow) * (QKVSTR * 4) + lcolo;
    const unsigned pbase = (unsigned)__cvta_generic_to_shared(pbuf)
                         + lrow * (PSTR * 4) + lcolo;

    // Q A-fragments: loaded once
    uint32_t qa[16];
    #pragma unroll
    for (int mt = 0; mt < 4; mt++) {
        uint32_t u[4];
        ldsm4(u, qbase + mt * 16 * QKVSTR * 4);
        #pragma unroll
        for (int i = 0; i < 4; i++) qa[4 * mt + i] = f2tf32(__uint_as_float(u[i]));
    }

    float oacc[16];
    float ssum[8];
    #pragma unroll
    for (int i = 0; i < 16; i++) oacc[i] = 0.f;
    #pragma unroll
    for (int i = 0; i < 8; i++) ssum[i] = 0.f;

    const int nkc  = 8 * (wblk + 1);
    const int dkc  = 8 * wblk;
    const int r1b  = 64 * wblk + (l >> 2);
    const int keyc = 2 * (l & 3);

    // S + exp2 for one 8-key chunk -> pr[16] (and ssum update)
    auto s_chunk = [&](int kc, float (&pr)[16]) {
        const int krow = 8 * kc + (l >> 2);
        uint32_t sb[2];
        sb[0] = f2tf32(qkv[krow * QKVSTR + 8 + (l & 3)]);
        sb[1] = f2tf32(qkv[krow * QKVSTR + 8 + (l & 3) + 4]);
        float sfr[16];
        #pragma unroll
        for (int i = 0; i < 16; i++) sfr[i] = 0.f;
        #pragma unroll
        for (int mt = 0; mt < 4; mt++)
            mma_tf32(&sfr[4 * mt], &qa[4 * mt], sb);
        const int key0 = 8 * kc + keyc;
        const bool diag = (kc >= dkc);
        #pragma unroll
        for (int mt = 0; mt < 4; mt++) {
            const int rr1 = r1b + 16 * mt, rr2 = rr1 + 8;
            float p0 = exp2f(sfr[4 * mt + 0]);
            float p1 = exp2f(sfr[4 * mt + 1]);
            float p2 = exp2f(sfr[4 * mt + 2]);
            float p3 = exp2f(sfr[4 * mt + 3]);
            if (diag) {
                p0 = (key0     <= rr1) ? p0 : 0.f;
                p1 = (key0 + 1 <= rr1) ? p1 : 0.f;
                p2 = (key0     <= rr2) ? p2 : 0.f;
                p3 = (key0 + 1 <= rr2) ? p3 : 0.f;
            }
            ssum[2 * mt]     += p0 + p1;
            ssum[2 * mt + 1] += p2 + p3;
            pr[4 * mt + 0] = p0; pr[4 * mt + 1] = p1;
            pr[4 * mt + 2] = p2; pr[4 * mt + 3] = p3;
        }
    };

    float prA[16], prB[16];
    s_chunk(0, prA);

    #pragma unroll 1
    for (int kc = 0; kc < nkc; kc++) {
        // write current P tile
        #pragma unroll
        for (int mt = 0; mt < 4; mt++) {
            float* pp = &pbuf[(16 * mt + (l >> 2)) * PSTR + keyc];
            *reinterpret_cast<float2*>(pp)            = make_float2(prA[4 * mt + 0], prA[4 * mt + 1]);
            *reinterpret_cast<float2*>(pp + 8 * PSTR) = make_float2(prA[4 * mt + 2], prA[4 * mt + 3]);
        }
        __syncwarp();

        // issue all LDSMs + V loads, then overlap their latency with S(kc+1)
        uint32_t u[16];
        #pragma unroll
        for (int mt = 0; mt < 4; mt++)
            ldsm4(&u[4 * mt], pbase + mt * 16 * PSTR * 4);
        uint32_t vb[2];
        vb[0] = f2tf32(qkv[(8 * kc + (l & 3)) * QKVSTR + 16 + (l >> 2)]);
        vb[1] = f2tf32(qkv[(8 * kc + (l & 3) + 4) * QKVSTR + 16 + (l >> 2)]);

        if (kc + 1 < nkc) s_chunk(kc + 1, prB);   // independent of pbuf/u

        // AV accumulate
        #pragma unroll
        for (int mt = 0; mt < 4; mt++) {
            uint32_t pa[4];
            #pragma unroll
            for (int i = 0; i < 4; i++) pa[i] = f2tf32(__uint_as_float(u[4 * mt + i]));
            mma_tf32(&oacc[4 * mt], pa, vb);
        }
        __syncwarp();   // WAR before next STS overwrites pbuf

        #pragma unroll
        for (int i = 0; i < 16; i++) prA[i] = prB[i];
    }

    // reduce row sums across the quad
    #pragma unroll
    for (int i = 0; i < 8; i++) {
        ssum[i] += __shfl_xor_sync(0xFFFFFFFF, ssum[i], 1);
        ssum[i] += __shfl_xor_sync(0xFFFFFFFF, ssum[i], 2);
    }

    // normalize + write O directly from C fragments
    float* ob = out + (long)b * TT * HH;
    #pragma unroll
    for (int mt = 0; mt < 4; mt++) {
        const int rr1 = r1b + 16 * mt;
        const float i1 = __fdividef(1.f, ssum[2 * mt]);
        const float i2 = __fdividef(1.f, ssum[2 * mt + 1]);
        *reinterpret_cast<float2*>(&ob[rr1 * HH + keyc]) =
            make_float2(oacc[4 * mt + 0] * i1, oacc[4 * mt + 1] * i1);
        *reinterpret_cast<float2*>(&ob[(rr1 + 8) * HH + keyc]) =
            make_float2(oacc[4 * mt + 2] * i2, oacc[4 * mt + 3] * i2);
    }
}

extern "C" void kernel_launch(void* const* d_in, const int* in_sizes, int n_in,
                              void* d_out, int out_size)
{
    const float* x  = (const float*)d_in[0];
    const float* Wq = (const float*)d_in[1];
    const float* Wk = (const float*)d_in[2];
    const float* Wv = (const float*)d_in[3];
    float* out = (float*)d_out;

    head_attn_kernel<<<1024, NT>>>(x, Wq, Wk, Wv, out);
}